// round 3
// baseline (speedup 1.0000x reference)
#include <cuda_runtime.h>
#include <cuda_fp16.h>
#include <cstdint>

#define NS     25
#define NQ     200
#define NITEM  (NS + NQ)        // 225
#define FF     80
#define DD     512
#define WAY    5
#define BLK    128
#define NBLK   10               // packed upper-tri 128x128 blocks of 4x4 grid
#define BLKSZ  (BLK * BLK)      // 16384
#define KPACK  (NBLK * BLKSZ)   // 163840
#define XPITCH 520              // smem pitch (halves): 512 + 8 pad
#define KCH    1024             // dot kernel K chunk
#define NKC    (KPACK / KCH)    // 160

// -------- scratch (__device__ globals; no allocations allowed) --------------
__device__ __half g_Gs[NS][KPACK];    // per-support packed Grams (offdiag x2)
__device__ __half g_Hp[NQ][KPACK];    // per-query packed Grams
__device__ __half g_Gc[WAY][KPACK];   // class-summed support Grams
__device__ float  g_bar[NITEM][DD];   // per-item feature-row sums (normalized)
__device__ float  g_sbarsum[WAY][DD];
__device__ int    g_cls_cnt[WAY];
__device__ int    g_cls_sup[WAY][NS];
__device__ float  g_S2[WAY][NQ];

__constant__ int c_bi[NBLK] = {0,0,0,0,1,1,1,2,2,3};
__constant__ int c_bj[NBLK] = {0,1,2,3,1,2,3,2,3,3};

// ---------------------------------------------------------------------------
__device__ __forceinline__ void ldsm_x4_t(uint32_t (&r)[4], const __half* p)
{
    uint32_t a = (uint32_t)__cvta_generic_to_shared(p);
    asm volatile("ldmatrix.sync.aligned.m8n8.x4.trans.shared.b16 {%0,%1,%2,%3}, [%4];"
                 : "=r"(r[0]), "=r"(r[1]), "=r"(r[2]), "=r"(r[3]) : "r"(a));
}

__device__ __forceinline__ void mma16816(float (&d)[4], const uint32_t (&a)[4],
                                         uint32_t b0, uint32_t b1)
{
    asm volatile("mma.sync.aligned.m16n8k16.row.col.f32.f16.f16.f32 "
                 "{%0,%1,%2,%3},{%4,%5,%6,%7},{%8,%9},{%0,%1,%2,%3};"
                 : "+f"(d[0]), "+f"(d[1]), "+f"(d[2]), "+f"(d[3])
                 : "r"(a[0]), "r"(a[1]), "r"(a[2]), "r"(a[3]), "r"(b0), "r"(b1));
}

// ---------------------------------------------------------------------------
// K1 (fused): one CTA per item. Normalize 80x512 fp32 -> fp16 smem, write
// feature-row sums, then compute all 10 packed Gram blocks from resident smem.
// ---------------------------------------------------------------------------
extern __shared__ char dynsmem[];

__global__ void __launch_bounds__(256, 2)
gram_kernel(const float* __restrict__ sg, const float* __restrict__ sl,
            const float* __restrict__ qg, const float* __restrict__ ql)
{
    __half* sX    = (__half*)dynsmem;                    // 80 x XPITCH halves
    float*  snorm = (float*)(dynsmem + FF * XPITCH * 2); // 80 floats

    const int item = blockIdx.x;
    const int tid  = threadIdx.x;
    const int lane = tid & 31;
    const int warp = tid >> 5;

    const float* gbase;
    const float* lbase;
    if (item < NS) { gbase = sg + (size_t)item * 16 * DD;        lbase = sl + (size_t)item * 64 * DD; }
    else           { int q = item - NS;
                     gbase = qg + (size_t)q * 16 * DD;           lbase = ql + (size_t)q * 64 * DD; }

    // ---- pass 1: per-row 1/||x|| ----
    for (int f = warp; f < FF; f += 8) {
        const float4* src = (const float4*)((f < 16) ? gbase + (size_t)f * DD
                                                     : lbase + (size_t)(f - 16) * DD);
        float ss = 0.f;
#pragma unroll
        for (int i = 0; i < 4; i++) {
            float4 v = src[lane + 32 * i];
            ss += v.x * v.x + v.y * v.y + v.z * v.z + v.w * v.w;
        }
#pragma unroll
        for (int o = 16; o; o >>= 1) ss += __shfl_xor_sync(0xFFFFFFFFu, ss, o);
        if (lane == 0) snorm[f] = rsqrtf(fmaxf(ss, 1e-24f));
    }
    __syncthreads();

    // ---- pass 2: scale + convert into fp16 smem (re-read hits L2) ----
    for (int ch = tid; ch < FF * 128; ch += 256) {
        int f = ch >> 7, c4 = ch & 127;
        const float4* src = (const float4*)((f < 16) ? gbase + (size_t)f * DD
                                                     : lbase + (size_t)(f - 16) * DD);
        float4 v = src[c4];
        float rn = snorm[f];
        __half2 hh[2];
        hh[0] = __floats2half2_rn(v.x * rn, v.y * rn);
        hh[1] = __floats2half2_rn(v.z * rn, v.w * rn);
        *(uint2*)&sX[f * XPITCH + c4 * 4] = *(uint2*)hh;
    }
    __syncthreads();

    // ---- feature-row sums (columns of sX) -> g_bar[item] ----
    {
        float sx = 0.f, sy = 0.f;
#pragma unroll 8
        for (int f = 0; f < FF; f++) {
            float2 v = __half22float2(*(const __half2*)&sX[f * XPITCH + 2 * tid]);
            sx += v.x; sy += v.y;
        }
        g_bar[item][2 * tid + 0] = sx;
        g_bar[item][2 * tid + 1] = sy;
    }

    // ---- 10 packed Gram blocks, no barriers (smem read-only from here) ----
    const int m_base = (warp >> 1) * 32;
    const int n_base = (warp & 1) * 64;
    const int a_krow = ((lane >> 4) << 3) + (lane & 7);
    const int a_coff = ((lane >> 3) & 1) << 3;
    const int b_krow = (((lane >> 3) & 1) << 3) + (lane & 7);
    const int b_coff = (lane >> 4) << 3;

#pragma unroll 1
    for (int b = 0; b < NBLK; b++) {
        const int ca = c_bi[b] * BLK;
        const int cb = c_bj[b] * BLK;

        float acc[2][8][4];
#pragma unroll
        for (int mt = 0; mt < 2; mt++)
#pragma unroll
            for (int nt = 0; nt < 8; nt++)
#pragma unroll
                for (int i = 0; i < 4; i++) acc[mt][nt][i] = 0.f;

#pragma unroll
        for (int k16 = 0; k16 < FF / 16; k16++) {
            const int k0 = k16 * 16;
            uint32_t a[2][4];
#pragma unroll
            for (int mt = 0; mt < 2; mt++)
                ldsm_x4_t(a[mt], &sX[(k0 + a_krow) * XPITCH + ca + m_base + mt * 16 + a_coff]);
#pragma unroll
            for (int nt = 0; nt < 4; nt++) {
                uint32_t bf[4];
                ldsm_x4_t(bf, &sX[(k0 + b_krow) * XPITCH + cb + n_base + nt * 16 + b_coff]);
#pragma unroll
                for (int mt = 0; mt < 2; mt++) {
                    mma16816(acc[mt][2 * nt + 0], a[mt], bf[0], bf[1]);
                    mma16816(acc[mt][2 * nt + 1], a[mt], bf[2], bf[3]);
                }
            }
        }

        const float scale = (item < NS && ca != cb) ? 2.f : 1.f;
        __half* out = ((item < NS) ? g_Gs[item] : g_Hp[item - NS]) + b * BLKSZ;
#pragma unroll
        for (int mt = 0; mt < 2; mt++) {
            int r = m_base + mt * 16 + (lane >> 2);
#pragma unroll
            for (int nt = 0; nt < 8; nt++) {
                int c = n_base + nt * 8 + (lane & 3) * 2;
                *(__half2*)(out + r * BLK + c) =
                    __floats2half2_rn(acc[mt][nt][0] * scale, acc[mt][nt][1] * scale);
                *(__half2*)(out + (r + 8) * BLK + c) =
                    __floats2half2_rn(acc[mt][nt][2] * scale, acc[mt][nt][3] * scale);
            }
        }
    }
}

// ---------------------------------------------------------------------------
// K2: class lists, class-summed row-sums, zero S2
// ---------------------------------------------------------------------------
__global__ void prep_kernel(const long long* __restrict__ labels)
{
    __shared__ int cnt[WAY];
    __shared__ int sup[WAY][NS];
    int t = threadIdx.x;  // 512
    if (t == 0) {
        for (int c = 0; c < WAY; c++) cnt[c] = 0;
        for (int s = 0; s < NS; s++) {
            int c = (int)labels[s];
            sup[c][cnt[c]++] = s;
        }
        for (int c = 0; c < WAY; c++) {
            g_cls_cnt[c] = cnt[c];
            for (int i = 0; i < cnt[c]; i++) g_cls_sup[c][i] = sup[c][i];
        }
    }
    __syncthreads();
    if (t < DD) {
#pragma unroll
        for (int c = 0; c < WAY; c++) {
            float a = 0.f;
            for (int i = 0; i < cnt[c]; i++) a += g_bar[sup[c][i]][t];
            g_sbarsum[c][t] = a;
        }
    }
    for (int i = t; i < WAY * NQ; i += blockDim.x)
        (&g_S2[0][0])[i] = 0.f;
}

// ---------------------------------------------------------------------------
// K3: class-sum the support Grams (fp32 accumulate, fp16 out)
// ---------------------------------------------------------------------------
__global__ void __launch_bounds__(256) classsum_kernel()
{
    const int c    = blockIdx.y;
    const int base = blockIdx.x * 4096 + threadIdx.x * 16;
    const int cnt  = g_cls_cnt[c];

    float acc[16];
#pragma unroll
    for (int i = 0; i < 16; i++) acc[i] = 0.f;

    for (int s = 0; s < cnt; s++) {
        const __half* src = g_Gs[g_cls_sup[c][s]] + base;
        int4 v0 = *(const int4*)(src);
        int4 v1 = *(const int4*)(src + 8);
        const __half2* h0 = (const __half2*)&v0;
        const __half2* h1 = (const __half2*)&v1;
#pragma unroll
        for (int j = 0; j < 4; j++) {
            float2 a = __half22float2(h0[j]);
            float2 b = __half22float2(h1[j]);
            acc[2 * j + 0] += a.x; acc[2 * j + 1] += a.y;
            acc[8 + 2 * j + 0] += b.x; acc[8 + 2 * j + 1] += b.y;
        }
    }
    __half out[16];
#pragma unroll
    for (int i = 0; i < 16; i++) out[i] = __float2half_rn(acc[i]);
    *(int4*)(g_Gc[c] + base)     = *(int4*)&out[0];
    *(int4*)(g_Gc[c] + base + 8) = *(int4*)&out[8];
}

// ---------------------------------------------------------------------------
// K4: split-K Frobenius dots. Grid = 160 K-chunks; G chunk resident in smem;
// each of 200 threads owns one query, streams H once, HFMA2 accumulate.
// ---------------------------------------------------------------------------
__global__ void __launch_bounds__(224) dot_kernel()
{
    __shared__ __half sG[WAY * KCH];
    const int k0  = blockIdx.x * KCH;
    const int tid = threadIdx.x;

    for (int idx = tid; idx < WAY * (KCH / 8); idx += 224) {
        int c = idx / (KCH / 8), o = idx % (KCH / 8);
        *(int4*)&sG[c * KCH + o * 8] = *(const int4*)&g_Gc[c][k0 + o * 8];
    }
    __syncthreads();

    if (tid < NQ) {
        const int4* H4 = (const int4*)(g_Hp[tid] + k0);
        __half2 acc[WAY][2];
#pragma unroll
        for (int c = 0; c < WAY; c++) {
            acc[c][0] = __floats2half2_rn(0.f, 0.f);
            acc[c][1] = __floats2half2_rn(0.f, 0.f);
        }
#pragma unroll 4
        for (int i = 0; i < KCH / 8; i++) {
            int4 hv = H4[i];
            const __half2* hh = (const __half2*)&hv;
#pragma unroll
            for (int c = 0; c < WAY; c++) {
                int4 gv = *(const int4*)&sG[c * KCH + i * 8];
                const __half2* gh = (const __half2*)&gv;
                acc[c][0] = __hfma2(gh[0], hh[0], acc[c][0]);
                acc[c][1] = __hfma2(gh[1], hh[1], acc[c][1]);
                acc[c][0] = __hfma2(gh[2], hh[2], acc[c][0]);
                acc[c][1] = __hfma2(gh[3], hh[3], acc[c][1]);
            }
        }
#pragma unroll
        for (int c = 0; c < WAY; c++) {
            float2 f0 = __half22float2(acc[c][0]);
            float2 f1 = __half22float2(acc[c][1]);
            atomicAdd(&g_S2[c][tid], f0.x + f0.y + f1.x + f1.y);
        }
    }
}

// ---------------------------------------------------------------------------
// K5: logits[q][c] = -2*F^2 + (4*S1 - 2*S2)/cnt. One warp per query.
// ---------------------------------------------------------------------------
__global__ void logits_kernel(float* __restrict__ out)
{
    int warp = (blockIdx.x * blockDim.x + threadIdx.x) >> 5;
    int lane = threadIdx.x & 31;
    if (warp >= NQ) return;
    const int q = warp;

    float s1[WAY] = {0.f, 0.f, 0.f, 0.f, 0.f};
    const float* qb = g_bar[NS + q];
    for (int k = lane; k < DD; k += 32) {
        float qv = qb[k];
#pragma unroll
        for (int c = 0; c < WAY; c++) s1[c] += g_sbarsum[c][k] * qv;
    }
#pragma unroll
    for (int o = 16; o; o >>= 1)
#pragma unroll
        for (int c = 0; c < WAY; c++)
            s1[c] += __shfl_xor_sync(0xFFFFFFFFu, s1[c], o);

    if (lane < WAY) {
        int c = lane;
        float cnt = (float)g_cls_cnt[c];
        out[q * WAY + c] = -2.f * (float)(FF * FF) + (4.f * s1[c] - 2.f * g_S2[c][q]) / cnt;
    }
}

// ---------------------------------------------------------------------------
extern "C" void kernel_launch(void* const* d_in, const int* in_sizes, int n_in,
                              void* d_out, int out_size)
{
    const float*     sg  = (const float*)d_in[0];
    const float*     sl  = (const float*)d_in[1];
    const long long* lab = (const long long*)d_in[2];
    const float*     qg  = (const float*)d_in[3];
    const float*     ql  = (const float*)d_in[4];
    float*           out = (float*)d_out;

    const int smem = FF * XPITCH * 2 + FF * 4 + 64;   // X tile + norms
    static bool attr_set = false;
    if (!attr_set) {
        cudaFuncSetAttribute(gram_kernel, cudaFuncAttributeMaxDynamicSharedMemorySize, smem);
        attr_set = true;
    }

    gram_kernel<<<NITEM, 256, smem>>>(sg, sl, qg, ql);   // 225 CTAs
    prep_kernel<<<1, 512>>>(lab);
    classsum_kernel<<<dim3(KPACK / 4096, WAY), 256>>>();
    dot_kernel<<<NKC, 224>>>();                          // 160 CTAs
    logits_kernel<<<(NQ * 32 + 255) / 256, 256>>>(out);
}